// round 1
// baseline (speedup 1.0000x reference)
#include <cuda_runtime.h>
#include <cstdint>

// ---------------------------------------------------------------------------
// SpikingAttention: adaptive-LIF (LSNN) scans + WTA pseudo-softmax
// B=32, T=1000, D=512, U=512
// ---------------------------------------------------------------------------

#define ALPHA 0.9f
#define RHO   0.995f
#define BETA  1.6f

#define NB 32
#define NT 1000
#define ND 512
#define NU 512
#define MTOT (NB*NT)          // 32000 rows

// d_out layout (floats), tuple flattened in order:
// out1 attention_spikes [B,T,512]          -> 16,384,000
// out2 all_spikes       [B,T,6*512]        -> 98,304,000
// out3 all_thr          [B,T,4*512]        -> 65,536,000
// out4 all_v_sc         [B,T,6*512]        -> 98,304,000
#define OUT1_OFF 0ull
#define OUT2_OFF 16384000ull
#define OUT3_OFF 114688000ull
#define OUT4_OFF 180224000ull

// Scratch (device globals; no allocation allowed)
__device__ float    g_I[3ll * MTOT * NU];     // feedforward currents k,q,v  (~197MB)
__device__ unsigned g_spk[3ll * MTOT * 16];   // spike bitmasks k,q,v (512 bits per (b,t))
__device__ unsigned g_zA[(long long)MTOT * 16]; // WTA pop-A spikes (one-hot-ish)

// ---------------------------------------------------------------------------
// SGEMM: C[m][n] = sum_k A[m][k] * W[k][n];  M=32000, K=512, N=512
// BM=128, BN=64, BK=16, 256 threads, 8x4 per-thread tile. Exact tiling (no guards).
// blockIdx.z selects which W / output slab (k,q,v).
// ---------------------------------------------------------------------------
__global__ __launch_bounds__(256) void sgemm_in_kernel(
    const float* __restrict__ A,
    const float* __restrict__ Wk,
    const float* __restrict__ Wq,
    const float* __restrict__ Wv)
{
    const float* __restrict__ W = (blockIdx.z == 0) ? Wk : (blockIdx.z == 1) ? Wq : Wv;
    float* __restrict__ C = g_I + (size_t)blockIdx.z * MTOT * NU;

    __shared__ float As[16][128];
    __shared__ float Bs[16][64];

    const int tid = threadIdx.x;
    const int m0 = blockIdx.x * 128;
    const int n0 = blockIdx.y * 64;
    const int tx = tid & 15;       // n: 16 groups * 4
    const int ty = tid >> 4;       // m: 16 groups * 8

    float acc[8][4];
#pragma unroll
    for (int i = 0; i < 8; i++)
#pragma unroll
        for (int j = 0; j < 4; j++) acc[i][j] = 0.f;

    for (int k0 = 0; k0 < 512; k0 += 16) {
        // Load A tile 128x16 (transposed into As[k][m]); 2 float4 per thread
#pragma unroll
        for (int l = 0; l < 2; l++) {
            int f   = tid * 2 + l;          // 0..511
            int row = f >> 2;               // 0..127
            int c4  = f & 3;                // 0..3
            float4 v = *(const float4*)(A + (size_t)(m0 + row) * 512 + k0 + c4 * 4);
            As[c4 * 4 + 0][row] = v.x;
            As[c4 * 4 + 1][row] = v.y;
            As[c4 * 4 + 2][row] = v.z;
            As[c4 * 4 + 3][row] = v.w;
        }
        // Load B tile 16x64; 1 float4 per thread
        {
            int row = tid >> 4;             // 0..15 (k)
            int c4  = tid & 15;             // 0..15
            float4 v = *(const float4*)(W + (size_t)(k0 + row) * 512 + n0 + c4 * 4);
            *(float4*)&Bs[row][c4 * 4] = v;
        }
        __syncthreads();

#pragma unroll
        for (int kk = 0; kk < 16; kk++) {
            float4 a0 = *(const float4*)&As[kk][ty * 8];
            float4 a1 = *(const float4*)&As[kk][ty * 8 + 4];
            float4 b0 = *(const float4*)&Bs[kk][tx * 4];
            float a[8] = {a0.x, a0.y, a0.z, a0.w, a1.x, a1.y, a1.z, a1.w};
            float b[4] = {b0.x, b0.y, b0.z, b0.w};
#pragma unroll
            for (int i = 0; i < 8; i++)
#pragma unroll
                for (int j = 0; j < 4; j++) acc[i][j] += a[i] * b[j];
        }
        __syncthreads();
    }

#pragma unroll
    for (int i = 0; i < 8; i++) {
        float4 v = make_float4(acc[i][0], acc[i][1], acc[i][2], acc[i][3]);
        *(float4*)(C + (size_t)(m0 + ty * 8 + i) * 512 + n0 + tx * 4) = v;
    }
}

// ---------------------------------------------------------------------------
// Deterministic spike-list builder. Called by lanes of warp 0 only (tid<32).
// mask: nw 32-bit words; writes indices (bias + bit position) into list starting
// at list_off. Returns total count (valid in all lanes).
// ---------------------------------------------------------------------------
__device__ __forceinline__ int warp_build_list(const unsigned* mask, int nw, int bias,
                                               unsigned short* list, int list_off)
{
    const int lane = threadIdx.x;   // caller guarantees tid < 32
    unsigned m = (lane < nw) ? mask[lane] : 0u;
    int c = __popc(m);
    int inc = c;
#pragma unroll
    for (int o = 1; o < 32; o <<= 1) {
        int v = __shfl_up_sync(0xffffffffu, inc, o);
        if (lane >= o) inc += v;
    }
    int off  = list_off + inc - c;   // exclusive prefix
    int base = bias + lane * 32;
    while (m) {
        int j = __ffs((int)m) - 1;
        list[off++] = (unsigned short)(base + j);
        m &= (m - 1);
    }
    return __shfl_sync(0xffffffffu, inc, 31);
}

// Coalesced row-gather: acc += sum over list entries of W[list[i]*512 + u]
__device__ __forceinline__ float gather_rows(const float* __restrict__ W,
                                             const unsigned short* list, int n,
                                             int u, float acc)
{
    int i = 0;
    int n4 = n & ~3;
    for (; i < n4; i += 4) {
        int j0 = list[i], j1 = list[i+1], j2 = list[i+2], j3 = list[i+3];
        float w0 = W[(size_t)j0 * 512 + u];
        float w1 = W[(size_t)j1 * 512 + u];
        float w2 = W[(size_t)j2 * 512 + u];
        float w3 = W[(size_t)j3 * 512 + u];
        acc += w0; acc += w1; acc += w2; acc += w3;
    }
    for (; i < n; i++) acc += W[(size_t)list[i] * 512 + u];
    return acc;
}

// ---------------------------------------------------------------------------
// LSNN scan for k,q,v. grid = (32 batches, 3 pops), 512 threads (thread = neuron)
// ---------------------------------------------------------------------------
__global__ __launch_bounds__(512) void lsnn_scan_kernel(
    const float* __restrict__ Wk_rec,
    const float* __restrict__ Wq_rec,
    const float* __restrict__ Wv_rec,
    float* __restrict__ d_out)
{
    const int b = blockIdx.x;
    const int p = blockIdx.y;
    const float* __restrict__ Wr = (p == 0) ? Wk_rec : (p == 1) ? Wq_rec : Wv_rec;
    const float* __restrict__ I  = g_I + (size_t)p * MTOT * NU + (size_t)b * NT * NU;
    unsigned* __restrict__ spk   = g_spk + (size_t)p * MTOT * 16 + (size_t)b * NT * 16;

    float* __restrict__ out2 = d_out + OUT2_OFF;
    float* __restrict__ out3 = d_out + OUT3_OFF;
    float* __restrict__ out4 = d_out + OUT4_OFF;

    const int tid = threadIdx.x;
    const int u = tid;
    const int warp = tid >> 5;
    const int lane = tid & 31;

    __shared__ unsigned mask[16];
    __shared__ unsigned short list[512];
    __shared__ int s_tot;

    if (tid < 16) mask[tid] = 0u;
    __syncthreads();

    float v = 0.f, a = 0.f, z = 0.f;

    for (int t = 0; t < NT; t++) {
        // Build list from z-ballots of previous step (mask already synced)
        if (tid < 32) {
            int tot = warp_build_list(mask, 16, 0, list, 0);
            if (tid == 0) s_tot = tot;
        }
        __syncthreads();
        const int nsp = s_tot;

        float acc = I[(size_t)t * NU + u];
        acc = gather_rows(Wr, list, nsp, u, acc);

        float a_new = RHO * a + z;
        float thr   = 1.0f + BETA * a_new;
        float v_new = ALPHA * v + acc - z * thr;
        float v_sc  = v_new - thr;            // B0 = 1
        float z_new = (v_sc > 0.f) ? 1.f : 0.f;

        const size_t base = (size_t)b * NT + t;
        out2[base * 3072 + (size_t)p * 512 + u] = z_new;
        out3[base * 2048 + (size_t)p * 512 + u] = thr;
        out4[base * 3072 + (size_t)p * 512 + u] = v_sc;

        unsigned bal = __ballot_sync(0xffffffffu, z_new > 0.f);
        if (lane == 0) {
            mask[warp] = bal;
            spk[(size_t)t * 16 + warp] = bal;
        }
        v = v_new; a = a_new; z = z_new;
        __syncthreads();   // list reads done; mask visible for next build
    }
}

// ---------------------------------------------------------------------------
// WTA scan. grid = 32 batches, 512 threads.
// ---------------------------------------------------------------------------
__global__ __launch_bounds__(512) void wta_scan_kernel(
    const float* __restrict__ Wa,
    const float* __restrict__ Wb,
    float* __restrict__ d_out)
{
    const int b = blockIdx.x;
    const unsigned* __restrict__ spkK = g_spk + (size_t)b * NT * 16;
    const unsigned* __restrict__ spkQ = g_spk + (size_t)1 * MTOT * 16 + (size_t)b * NT * 16;
    unsigned* __restrict__ zAout      = g_zA + (size_t)b * NT * 16;

    float* __restrict__ out2 = d_out + OUT2_OFF;
    float* __restrict__ out4 = d_out + OUT4_OFF;

    const int tid = threadIdx.x;
    const int u = tid;
    const int warp = tid >> 5;
    const int lane = tid & 31;

    __shared__ unsigned mask[32];
    __shared__ unsigned short list[1024];
    __shared__ int s_tot;
    __shared__ float red[16];
    __shared__ float s_max;

    float vA = 0.f, vB = 0.f, zA = 0.f, zB = 0.f;

    for (int t = 0; t < NT; t++) {
        if (tid < 16)      mask[tid] = spkK[(size_t)t * 16 + tid];
        else if (tid < 32) mask[tid] = spkQ[(size_t)t * 16 + (tid - 16)];
        __syncthreads();                                   // S1

        if (tid < 32) {
            int tot = warp_build_list(mask, 32, 0, list, 0);
            if (tid == 0) s_tot = tot;
        }
        __syncthreads();                                   // S2
        const int nsp = s_tot;

        float acc = gather_rows(Wa, list, nsp, u, 0.f);

        float vA_new = ALPHA * vA + acc - zA;              // B0 = 1
        float v_sc_A = vA_new - 1.0f;

        // exact block max of vA_new
        float m = vA_new;
#pragma unroll
        for (int o = 16; o > 0; o >>= 1) m = fmaxf(m, __shfl_xor_sync(0xffffffffu, m, o));
        if (lane == 0) red[warp] = m;
        __syncthreads();                                   // S3 (gather + list reads done)
        if (tid < 32) {
            float mm = (tid < 16) ? red[tid] : -3.402823466e38f;
#pragma unroll
            for (int o = 16; o > 0; o >>= 1) mm = fmaxf(mm, __shfl_xor_sync(0xffffffffu, mm, o));
            if (tid == 0) s_max = mm;
        }
        __syncthreads();                                   // S4

        float winner = (vA_new == s_max) ? 1.f : 0.f;
        float zA_new = (v_sc_A > 0.f) ? winner : 0.f;

        unsigned balA = __ballot_sync(0xffffffffu, zA_new > 0.f);
        if (lane == 0) {
            mask[warp]  = balA;                             // reuse words 0..15
            zAout[(size_t)t * 16 + warp] = balA;
        }
        __syncthreads();                                   // S5

        if (tid < 32) {
            int tot = warp_build_list(mask, 16, 0, list, 0);
            if (tid == 0) s_tot = tot;
        }
        __syncthreads();                                   // S6
        const int nspA = s_tot;

        float accB = gather_rows(Wb, list, nspA, u, 0.f);
        float vB_new = ALPHA * vB + accB - zB;
        float v_sc_B = vB_new - 1.0f;
        float zB_new = (v_sc_B > 0.f) ? 1.f : 0.f;

        const size_t base = (size_t)b * NT + t;
        out2[base * 3072 + 3 * 512 + u] = zA_new;
        out2[base * 3072 + 4 * 512 + u] = zB_new;
        out4[base * 3072 + 3 * 512 + u] = v_sc_A;
        out4[base * 3072 + 4 * 512 + u] = v_sc_B;

        vA = vA_new; vB = vB_new; zA = zA_new; zB = zB_new;
        __syncthreads();                                   // S7
    }
}

// ---------------------------------------------------------------------------
// Attention LSNN scan. grid = 32 batches, 512 threads.
// Input current: rows of Watt_in selected by [zV | zA], recurrent: Watt_rec by own z.
// ---------------------------------------------------------------------------
__global__ __launch_bounds__(512) void att_scan_kernel(
    const float* __restrict__ Win,
    const float* __restrict__ Wrec,
    float* __restrict__ d_out)
{
    const int b = blockIdx.x;
    const unsigned* __restrict__ spkV = g_spk + (size_t)2 * MTOT * 16 + (size_t)b * NT * 16;
    const unsigned* __restrict__ zAin = g_zA + (size_t)b * NT * 16;

    float* __restrict__ out1 = d_out + OUT1_OFF;
    float* __restrict__ out2 = d_out + OUT2_OFF;
    float* __restrict__ out3 = d_out + OUT3_OFF;
    float* __restrict__ out4 = d_out + OUT4_OFF;

    const int tid = threadIdx.x;
    const int u = tid;
    const int warp = tid >> 5;
    const int lane = tid & 31;

    __shared__ unsigned mask[48];          // [0..15]=zV, [16..31]=zA, [32..47]=recurrent z
    __shared__ unsigned short list[1536];  // indices <1024 -> Win row, >=1024 -> Wrec row-1024
    __shared__ int s_tot;

    if (tid < 16) mask[32 + tid] = 0u;
    __syncthreads();

    float v = 0.f, a = 0.f, z = 0.f;

    for (int t = 0; t < NT; t++) {
        if (tid < 16)      mask[tid] = spkV[(size_t)t * 16 + tid];
        else if (tid < 32) mask[tid] = zAin[(size_t)t * 16 + (tid - 16)];
        __syncthreads();                                   // S1

        if (tid < 32) {
            int t1 = warp_build_list(mask,      32, 0,    list, 0);
            int t2 = warp_build_list(mask + 32, 16, 1024, list, t1);
            if (tid == 0) s_tot = t1 + t2;
        }
        __syncthreads();                                   // S2
        const int nsp = s_tot;

        float acc = 0.f;
        {
            int i = 0;
            int n4 = nsp & ~3;
            for (; i < n4; i += 4) {
                int j0 = list[i], j1 = list[i+1], j2 = list[i+2], j3 = list[i+3];
                const float* r0 = (j0 < 1024) ? (Win + (size_t)j0 * 512) : (Wrec + (size_t)(j0 - 1024) * 512);
                const float* r1 = (j1 < 1024) ? (Win + (size_t)j1 * 512) : (Wrec + (size_t)(j1 - 1024) * 512);
                const float* r2 = (j2 < 1024) ? (Win + (size_t)j2 * 512) : (Wrec + (size_t)(j2 - 1024) * 512);
                const float* r3 = (j3 < 1024) ? (Win + (size_t)j3 * 512) : (Wrec + (size_t)(j3 - 1024) * 512);
                float w0 = r0[u], w1 = r1[u], w2 = r2[u], w3 = r3[u];
                acc += w0; acc += w1; acc += w2; acc += w3;
            }
            for (; i < nsp; i++) {
                int j = list[i];
                const float* r = (j < 1024) ? (Win + (size_t)j * 512) : (Wrec + (size_t)(j - 1024) * 512);
                acc += r[u];
            }
        }

        float a_new = RHO * a + z;
        float thr   = 1.0f + BETA * a_new;
        float v_new = ALPHA * v + acc - z * thr;
        float v_sc  = v_new - thr;
        float z_new = (v_sc > 0.f) ? 1.f : 0.f;

        const size_t base = (size_t)b * NT + t;
        out1[base * 512 + u]                 = z_new;
        out2[base * 3072 + 5 * 512 + u]      = z_new;
        out3[base * 2048 + 3 * 512 + u]      = thr;
        out4[base * 3072 + 5 * 512 + u]      = v_sc;

        unsigned bal = __ballot_sync(0xffffffffu, z_new > 0.f);
        if (lane == 0) mask[32 + warp] = bal;
        v = v_new; a = a_new; z = z_new;
        __syncthreads();                                   // S3
    }
}

// ---------------------------------------------------------------------------
extern "C" void kernel_launch(void* const* d_in, const int* in_sizes, int n_in,
                              void* d_out, int out_size)
{
    const float* x        = (const float*)d_in[0];
    const float* Wk_in    = (const float*)d_in[1];
    const float* Wk_rec   = (const float*)d_in[2];
    const float* Wq_in    = (const float*)d_in[3];
    const float* Wq_rec   = (const float*)d_in[4];
    const float* Wv_in    = (const float*)d_in[5];
    const float* Wv_rec   = (const float*)d_in[6];
    const float* Watt_in  = (const float*)d_in[7];
    const float* Watt_rec = (const float*)d_in[8];
    const float* Wwta_a   = (const float*)d_in[9];
    const float* Wwta_b   = (const float*)d_in[10];
    float* out = (float*)d_out;

    (void)in_sizes; (void)n_in; (void)out_size;

    // Phase A: feedforward currents for k,q,v
    dim3 gA(MTOT / 128, 512 / 64, 3);
    sgemm_in_kernel<<<gA, 256>>>(x, Wk_in, Wq_in, Wv_in);

    // Phase B: k,q,v LSNN scans (independent, one launch)
    dim3 gB(NB, 3);
    lsnn_scan_kernel<<<gB, 512>>>(Wk_rec, Wq_rec, Wv_rec, out);

    // Phase C: WTA scan (needs zK, zQ)
    wta_scan_kernel<<<NB, 512>>>(Wwta_a, Wwta_b, out);

    // Phase D: attention LSNN scan (needs zV, zA)
    att_scan_kernel<<<NB, 512>>>(Watt_in, Watt_rec, out);
}

// round 2
// speedup vs baseline: 1.0625x; 1.0625x over previous
#include <cuda_runtime.h>
#include <cstdint>

// ---------------------------------------------------------------------------
// SpikingAttention: adaptive-LIF (LSNN) scans + WTA pseudo-softmax
// B=32, T=1000, D=512, U=512
// ---------------------------------------------------------------------------

#define ALPHA 0.9f
#define RHO   0.995f
#define BETA  1.6f

#define NB 32
#define NT 1000
#define ND 512
#define NU 512
#define MTOT (NB*NT)          // 32000 rows

// d_out layout (floats):
#define OUT1_OFF 0ull
#define OUT2_OFF 16384000ull
#define OUT3_OFF 114688000ull
#define OUT4_OFF 180224000ull

// Scratch (device globals; no allocation allowed)
__device__ float    g_I[3ll * MTOT * NU];       // feedforward currents k,q,v
__device__ unsigned g_spk[3ll * MTOT * 16];     // spike bitmasks k,q,v
__device__ unsigned g_zA[(long long)MTOT * 16]; // WTA pop-A spikes
__device__ int      g_prog[128];                // progress flags [pop*32+b], pops: 0=k,1=q,2=v,3=zA

// ---------------------------------------------------------------------------
// f32x2 packed FMA helpers (sm_100+; ptxas never auto-fuses — PTX only)
// ---------------------------------------------------------------------------
#define FMA_F32X2(acc, a, b) \
    asm("fma.rn.f32x2 %0, %1, %2, %0;" : "+l"(acc) : "l"(a), "l"(b))
#define PACK_DUP2(out, f) \
    asm("mov.b64 %0, {%1, %1};" : "=l"(out) : "f"(f))

// ---------------------------------------------------------------------------
// SGEMM: C[m][n] = sum_k A[m][k] * W[k][n];  M=32000, K=512, N=512
// BM=128, BN=128, BK=16, 256 threads, 8x8 per thread via packed f32x2 FMA.
// blockIdx.z selects which W / output slab (k,q,v).
// ---------------------------------------------------------------------------
__global__ __launch_bounds__(256, 2) void sgemm_in_kernel(
    const float* __restrict__ A,
    const float* __restrict__ Wk,
    const float* __restrict__ Wq,
    const float* __restrict__ Wv)
{
    const float* __restrict__ W = (blockIdx.z == 0) ? Wk : (blockIdx.z == 1) ? Wq : Wv;
    float* __restrict__ C = g_I + (size_t)blockIdx.z * MTOT * NU;

    __shared__ float As[16][128];   // transposed: As[k][m]
    __shared__ float Bs[16][128];   // Bs[k][n]

    const int tid = threadIdx.x;
    const int m0 = blockIdx.x * 128;
    const int n0 = blockIdx.y * 128;
    const int tx = tid & 15;        // n group (8 cols)
    const int ty = tid >> 4;        // m group (8 rows)

    unsigned long long acc[8][4];
#pragma unroll
    for (int i = 0; i < 8; i++)
#pragma unroll
        for (int j = 0; j < 4; j++) acc[i][j] = 0ull;

    float4 pa[2], pb[2];

    // prefetch tile k0 into registers
    {
#pragma unroll
        for (int l = 0; l < 2; l++) {
            int f = l * 256 + tid;
            int row = f >> 2, c4 = f & 3;                 // A: 128 rows x 4 float4
            pa[l] = *(const float4*)(A + (size_t)(m0 + row) * 512 + c4 * 4);
            int rb = f >> 5, cb = f & 31;                 // B: 16 rows x 32 float4
            pb[l] = *(const float4*)(W + (size_t)rb * 512 + n0 + cb * 4);
        }
    }
    // store to smem
#pragma unroll
    for (int l = 0; l < 2; l++) {
        int f = l * 256 + tid;
        int row = f >> 2, c4 = f & 3;
        As[c4 * 4 + 0][row] = pa[l].x;
        As[c4 * 4 + 1][row] = pa[l].y;
        As[c4 * 4 + 2][row] = pa[l].z;
        As[c4 * 4 + 3][row] = pa[l].w;
        int rb = f >> 5, cb = f & 31;
        *(float4*)&Bs[rb][cb * 4] = pb[l];
    }
    __syncthreads();

    for (int kt = 0; kt < 32; kt++) {
        if (kt < 31) {
            int k0 = (kt + 1) * 16;
#pragma unroll
            for (int l = 0; l < 2; l++) {
                int f = l * 256 + tid;
                int row = f >> 2, c4 = f & 3;
                pa[l] = *(const float4*)(A + (size_t)(m0 + row) * 512 + k0 + c4 * 4);
                int rb = f >> 5, cb = f & 31;
                pb[l] = *(const float4*)(W + (size_t)(k0 + rb) * 512 + n0 + cb * 4);
            }
        }

#pragma unroll
        for (int kk = 0; kk < 16; kk++) {
            float4 a0 = *(const float4*)&As[kk][ty * 8];
            float4 a1 = *(const float4*)&As[kk][ty * 8 + 4];
            ulonglong2 b0 = *(const ulonglong2*)&Bs[kk][tx * 8];      // cols 0-3 as 2 pairs
            ulonglong2 b1 = *(const ulonglong2*)&Bs[kk][tx * 8 + 4];  // cols 4-7
            unsigned long long bp[4] = {b0.x, b0.y, b1.x, b1.y};
            float av[8] = {a0.x, a0.y, a0.z, a0.w, a1.x, a1.y, a1.z, a1.w};
#pragma unroll
            for (int i = 0; i < 8; i++) {
                unsigned long long ad;
                PACK_DUP2(ad, av[i]);
#pragma unroll
                for (int j = 0; j < 4; j++) FMA_F32X2(acc[i][j], ad, bp[j]);
            }
        }
        __syncthreads();

        if (kt < 31) {
#pragma unroll
            for (int l = 0; l < 2; l++) {
                int f = l * 256 + tid;
                int row = f >> 2, c4 = f & 3;
                As[c4 * 4 + 0][row] = pa[l].x;
                As[c4 * 4 + 1][row] = pa[l].y;
                As[c4 * 4 + 2][row] = pa[l].z;
                As[c4 * 4 + 3][row] = pa[l].w;
                int rb = f >> 5, cb = f & 31;
                *(float4*)&Bs[rb][cb * 4] = pb[l];
            }
            __syncthreads();
        }
    }

#pragma unroll
    for (int i = 0; i < 8; i++) {
        float* Crow = C + (size_t)(m0 + ty * 8 + i) * 512 + n0 + tx * 8;
        ulonglong2 v0; v0.x = acc[i][0]; v0.y = acc[i][1];
        ulonglong2 v1; v1.x = acc[i][2]; v1.y = acc[i][3];
        *(ulonglong2*)Crow = v0;
        *((ulonglong2*)Crow + 1) = v1;
    }
}

// ---------------------------------------------------------------------------
// Progress-flag helpers (release: fence after block barrier; acquire: fence)
// ---------------------------------------------------------------------------
__device__ __forceinline__ void publish(int pop, int b, int tplus1)
{
    __threadfence();
    *(volatile int*)&g_prog[pop * 32 + b] = tplus1;
}
__device__ __forceinline__ void wait_for(int pop, int b, int tplus1)
{
    volatile int* f = &g_prog[pop * 32 + b];
    while (*f < tplus1) { __nanosleep(40); }
    __threadfence();
}

__global__ void reset_kernel()
{
    if (threadIdx.x < 128) g_prog[threadIdx.x] = 0;
}

// ---------------------------------------------------------------------------
// Deterministic spike-list builder (warp 0 lanes only).
// ---------------------------------------------------------------------------
__device__ __forceinline__ int warp_build_list(const unsigned* mask, int nw, int bias,
                                               unsigned short* list, int list_off)
{
    const int lane = threadIdx.x;
    unsigned m = (lane < nw) ? mask[lane] : 0u;
    int c = __popc(m);
    int inc = c;
#pragma unroll
    for (int o = 1; o < 32; o <<= 1) {
        int v = __shfl_up_sync(0xffffffffu, inc, o);
        if (lane >= o) inc += v;
    }
    int off  = list_off + inc - c;
    int base = bias + lane * 32;
    while (m) {
        int j = __ffs((int)m) - 1;
        list[off++] = (unsigned short)(base + j);
        m &= (m - 1);
    }
    return __shfl_sync(0xffffffffu, inc, 31);
}

__device__ __forceinline__ float gather_rows(const float* __restrict__ W,
                                             const unsigned short* list, int n,
                                             int u, float acc)
{
    int i = 0;
    int n4 = n & ~3;
    for (; i < n4; i += 4) {
        int j0 = list[i], j1 = list[i+1], j2 = list[i+2], j3 = list[i+3];
        float w0 = W[(size_t)j0 * 512 + u];
        float w1 = W[(size_t)j1 * 512 + u];
        float w2 = W[(size_t)j2 * 512 + u];
        float w3 = W[(size_t)j3 * 512 + u];
        acc += w0; acc += w1; acc += w2; acc += w3;
    }
    for (; i < n; i++) acc += W[(size_t)list[i] * 512 + u];
    return acc;
}

// ---------------------------------------------------------------------------
// Fused scan kernel: 160 blocks, 512 threads.
//   blocks [0,96):   lsnn p=bid/32, b=bid%32   (producers)
//   blocks [96,128): wta  b=bid-96             (consumes k,q; produces zA)
//   blocks [128,160):att  b=bid-128            (consumes v, zA)
// All 160 blocks co-resident (4 blocks/SM capacity); producers never wait on
// consumers -> deadlock-free pipelined execution.
// ---------------------------------------------------------------------------
__device__ void lsnn_body(int p, int b,
                          const float* __restrict__ Wr,
                          float* __restrict__ d_out)
{
    const float* __restrict__ I  = g_I + (size_t)p * MTOT * NU + (size_t)b * NT * NU;
    unsigned* __restrict__ spk   = g_spk + (size_t)p * MTOT * 16 + (size_t)b * NT * 16;

    float* __restrict__ out2 = d_out + OUT2_OFF;
    float* __restrict__ out3 = d_out + OUT3_OFF;
    float* __restrict__ out4 = d_out + OUT4_OFF;

    const int tid = threadIdx.x;
    const int u = tid;
    const int warp = tid >> 5;
    const int lane = tid & 31;

    __shared__ unsigned mask[16];
    __shared__ unsigned short list[512];
    __shared__ int s_tot;

    if (tid < 16) mask[tid] = 0u;
    __syncthreads();

    float v = 0.f, a = 0.f, z = 0.f;

    for (int t = 0; t < NT; t++) {
        if (tid < 32) {
            int tot = warp_build_list(mask, 16, 0, list, 0);
            if (tid == 0) s_tot = tot;
        }
        __syncthreads();
        const int nsp = s_tot;

        float acc = I[(size_t)t * NU + u];
        acc = gather_rows(Wr, list, nsp, u, acc);

        float a_new = RHO * a + z;
        float thr   = 1.0f + BETA * a_new;
        float v_new = ALPHA * v + acc - z * thr;
        float v_sc  = v_new - thr;
        float z_new = (v_sc > 0.f) ? 1.f : 0.f;

        const size_t base = (size_t)b * NT + t;
        out2[base * 3072 + (size_t)p * 512 + u] = z_new;
        out3[base * 2048 + (size_t)p * 512 + u] = thr;
        out4[base * 3072 + (size_t)p * 512 + u] = v_sc;

        unsigned bal = __ballot_sync(0xffffffffu, z_new > 0.f);
        if (lane == 0) {
            mask[warp] = bal;
            spk[(size_t)t * 16 + warp] = bal;
        }
        v = v_new; a = a_new; z = z_new;
        __syncthreads();
        if (tid == 0) publish(p, b, t + 1);
    }
}

__device__ void wta_body(int b,
                         const float* __restrict__ Wa,
                         const float* __restrict__ Wb,
                         float* __restrict__ d_out)
{
    const unsigned* __restrict__ spkK = g_spk + (size_t)b * NT * 16;
    const unsigned* __restrict__ spkQ = g_spk + (size_t)1 * MTOT * 16 + (size_t)b * NT * 16;
    unsigned* __restrict__ zAout      = g_zA + (size_t)b * NT * 16;

    float* __restrict__ out2 = d_out + OUT2_OFF;
    float* __restrict__ out4 = d_out + OUT4_OFF;

    const int tid = threadIdx.x;
    const int u = tid;
    const int warp = tid >> 5;
    const int lane = tid & 31;

    __shared__ unsigned maskW[32];
    __shared__ unsigned short listW[1024];
    __shared__ int s_totW;
    __shared__ float red[16];
    __shared__ float s_max;

    float vA = 0.f, vB = 0.f, zA = 0.f, zB = 0.f;

    for (int t = 0; t < NT; t++) {
        if (tid < 2) wait_for(tid, b, t + 1);      // tid0: k, tid1: q
        __syncthreads();

        if (tid < 16)      maskW[tid] = __ldcg(&spkK[(size_t)t * 16 + tid]);
        else if (tid < 32) maskW[tid] = __ldcg(&spkQ[(size_t)t * 16 + (tid - 16)]);
        __syncthreads();

        if (tid < 32) {
            int tot = warp_build_list(maskW, 32, 0, listW, 0);
            if (tid == 0) s_totW = tot;
        }
        __syncthreads();
        const int nsp = s_totW;

        float acc = gather_rows(Wa, listW, nsp, u, 0.f);

        float vA_new = ALPHA * vA + acc - zA;
        float v_sc_A = vA_new - 1.0f;

        float m = vA_new;
#pragma unroll
        for (int o = 16; o > 0; o >>= 1) m = fmaxf(m, __shfl_xor_sync(0xffffffffu, m, o));
        if (lane == 0) red[warp] = m;
        __syncthreads();
        if (tid < 32) {
            float mm = (tid < 16) ? red[tid] : -3.402823466e38f;
#pragma unroll
            for (int o = 16; o > 0; o >>= 1) mm = fmaxf(mm, __shfl_xor_sync(0xffffffffu, mm, o));
            if (tid == 0) s_max = mm;
        }
        __syncthreads();

        float winner = (vA_new == s_max) ? 1.f : 0.f;
        float zA_new = (v_sc_A > 0.f) ? winner : 0.f;

        unsigned balA = __ballot_sync(0xffffffffu, zA_new > 0.f);
        if (lane == 0) {
            maskW[warp] = balA;
            zAout[(size_t)t * 16 + warp] = balA;
        }
        __syncthreads();
        if (tid == 0) publish(3, b, t + 1);

        if (tid < 32) {
            int tot = warp_build_list(maskW, 16, 0, listW, 0);
            if (tid == 0) s_totW = tot;
        }
        __syncthreads();
        const int nspA = s_totW;

        float accB = gather_rows(Wb, listW, nspA, u, 0.f);
        float vB_new = ALPHA * vB + accB - zB;
        float v_sc_B = vB_new - 1.0f;
        float zB_new = (v_sc_B > 0.f) ? 1.f : 0.f;

        const size_t base = (size_t)b * NT + t;
        out2[base * 3072 + 3 * 512 + u] = zA_new;
        out2[base * 3072 + 4 * 512 + u] = zB_new;
        out4[base * 3072 + 3 * 512 + u] = v_sc_A;
        out4[base * 3072 + 4 * 512 + u] = v_sc_B;

        vA = vA_new; vB = vB_new; zA = zA_new; zB = zB_new;
        __syncthreads();
    }
}

__device__ void att_body(int b,
                         const float* __restrict__ Win,
                         const float* __restrict__ Wrec,
                         float* __restrict__ d_out)
{
    const unsigned* __restrict__ spkV = g_spk + (size_t)2 * MTOT * 16 + (size_t)b * NT * 16;
    const unsigned* __restrict__ zAin = g_zA + (size_t)b * NT * 16;

    float* __restrict__ out1 = d_out + OUT1_OFF;
    float* __restrict__ out2 = d_out + OUT2_OFF;
    float* __restrict__ out3 = d_out + OUT3_OFF;
    float* __restrict__ out4 = d_out + OUT4_OFF;

    const int tid = threadIdx.x;
    const int u = tid;
    const int warp = tid >> 5;
    const int lane = tid & 31;

    __shared__ unsigned maskA[48];          // [0..15]=zV, [16..31]=zA, [32..47]=own z
    __shared__ unsigned short listA[1536];
    __shared__ int s_totA;

    if (tid < 16) maskA[32 + tid] = 0u;
    __syncthreads();

    float v = 0.f, a = 0.f, z = 0.f;

    for (int t = 0; t < NT; t++) {
        if (tid < 2) wait_for(2 + tid, b, t + 1);   // tid0: v, tid1: zA
        __syncthreads();

        if (tid < 16)      maskA[tid] = __ldcg(&spkV[(size_t)t * 16 + tid]);
        else if (tid < 32) maskA[tid] = __ldcg(&zAin[(size_t)t * 16 + (tid - 16)]);
        __syncthreads();

        if (tid < 32) {
            int t1 = warp_build_list(maskA,      32, 0,    listA, 0);
            int t2 = warp_build_list(maskA + 32, 16, 1024, listA, t1);
            if (tid == 0) s_totA = t1 + t2;
        }
        __syncthreads();
        const int nsp = s_totA;

        float acc = 0.f;
        {
            int i = 0;
            int n4 = nsp & ~3;
            for (; i < n4; i += 4) {
                int j0 = listA[i], j1 = listA[i+1], j2 = listA[i+2], j3 = listA[i+3];
                const float* r0 = (j0 < 1024) ? (Win + (size_t)j0 * 512) : (Wrec + (size_t)(j0 - 1024) * 512);
                const float* r1 = (j1 < 1024) ? (Win + (size_t)j1 * 512) : (Wrec + (size_t)(j1 - 1024) * 512);
                const float* r2 = (j2 < 1024) ? (Win + (size_t)j2 * 512) : (Wrec + (size_t)(j2 - 1024) * 512);
                const float* r3 = (j3 < 1024) ? (Win + (size_t)j3 * 512) : (Wrec + (size_t)(j3 - 1024) * 512);
                float w0 = r0[u], w1 = r1[u], w2 = r2[u], w3 = r3[u];
                acc += w0; acc += w1; acc += w2; acc += w3;
            }
            for (; i < nsp; i++) {
                int j = listA[i];
                const float* r = (j < 1024) ? (Win + (size_t)j * 512) : (Wrec + (size_t)(j - 1024) * 512);
                acc += r[u];
            }
        }

        float a_new = RHO * a + z;
        float thr   = 1.0f + BETA * a_new;
        float v_new = ALPHA * v + acc - z * thr;
        float v_sc  = v_new - thr;
        float z_new = (v_sc > 0.f) ? 1.f : 0.f;

        const size_t base = (size_t)b * NT + t;
        out1[base * 512 + u]            = z_new;
        out2[base * 3072 + 5 * 512 + u] = z_new;
        out3[base * 2048 + 3 * 512 + u] = thr;
        out4[base * 3072 + 5 * 512 + u] = v_sc;

        unsigned bal = __ballot_sync(0xffffffffu, z_new > 0.f);
        if (lane == 0) maskA[32 + warp] = bal;
        v = v_new; a = a_new; z = z_new;
        __syncthreads();
    }
}

__global__ __launch_bounds__(512) void fused_scan_kernel(
    const float* __restrict__ Wk_rec,
    const float* __restrict__ Wq_rec,
    const float* __restrict__ Wv_rec,
    const float* __restrict__ Wwta_a,
    const float* __restrict__ Wwta_b,
    const float* __restrict__ Watt_in,
    const float* __restrict__ Watt_rec,
    float* __restrict__ d_out)
{
    const int bid = blockIdx.x;
    if (bid < 96) {
        const int p = bid >> 5, b = bid & 31;
        const float* Wr = (p == 0) ? Wk_rec : (p == 1) ? Wq_rec : Wv_rec;
        lsnn_body(p, b, Wr, d_out);
    } else if (bid < 128) {
        wta_body(bid - 96, Wwta_a, Wwta_b, d_out);
    } else {
        att_body(bid - 128, Watt_in, Watt_rec, d_out);
    }
}

// ---------------------------------------------------------------------------
extern "C" void kernel_launch(void* const* d_in, const int* in_sizes, int n_in,
                              void* d_out, int out_size)
{
    const float* x        = (const float*)d_in[0];
    const float* Wk_in    = (const float*)d_in[1];
    const float* Wk_rec   = (const float*)d_in[2];
    const float* Wq_in    = (const float*)d_in[3];
    const float* Wq_rec   = (const float*)d_in[4];
    const float* Wv_in    = (const float*)d_in[5];
    const float* Wv_rec   = (const float*)d_in[6];
    const float* Watt_in  = (const float*)d_in[7];
    const float* Watt_rec = (const float*)d_in[8];
    const float* Wwta_a   = (const float*)d_in[9];
    const float* Wwta_b   = (const float*)d_in[10];
    float* out = (float*)d_out;

    (void)in_sizes; (void)n_in; (void)out_size;

    // Phase A: feedforward currents for k,q,v (f32x2 packed GEMM)
    dim3 gA(MTOT / 128, 512 / 128, 3);
    sgemm_in_kernel<<<gA, 256>>>(x, Wk_in, Wq_in, Wv_in);

    // Reset progress flags
    reset_kernel<<<1, 128>>>();

    // Phase B: fused pipelined scans (lsnn k/q/v + wta + att overlap)
    fused_scan_kernel<<<160, 512>>>(Wk_rec, Wq_rec, Wv_rec,
                                    Wwta_a, Wwta_b, Watt_in, Watt_rec, out);
}

// round 3
// speedup vs baseline: 1.1620x; 1.0936x over previous
#include <cuda_runtime.h>
#include <cstdint>

// ---------------------------------------------------------------------------
// SpikingAttention: adaptive-LIF (LSNN) scans + WTA pseudo-softmax
// B=32, T=1000, D=512, U=512
// Single fused kernel: blocks 0..159 = scan roles, blocks 160..3159 = GEMM.
// GEMM produces feedforward currents in t-chunk order (4 t's per chunk) and
// publishes chunk counters; scans consume progressively. Scans never block
// GEMM -> deadlock-free. Cross-block sync via st.release/ld.acquire (gpu scope).
// ---------------------------------------------------------------------------

#define ALPHA 0.9f
#define RHO   0.995f
#define BETA  1.6f

#define NB 32
#define NT 1000
#define NU 512
#define MTOT (NB*NT)          // 32000

#define OUT1_OFF 0ull
#define OUT2_OFF 16384000ull
#define OUT3_OFF 114688000ull
#define OUT4_OFF 180224000ull

// Scratch
__device__ float    g_I[3ll * MTOT * NU];        // currents, layout [pop][t][b][u]
__device__ unsigned g_spk[3ll * MTOT * 16];      // spike masks [pop][b][t][16]
__device__ unsigned g_zA[(long long)MTOT * 16];  // WTA pop-A spikes [b][t][16]
__device__ int      g_flag[128];                 // per-(pop,b) step progress; pops 0=k,1=q,2=v,3=zA
__device__ int      g_chunk[3 * 250];            // per-(pop, t-chunk of 4) GEMM n-tile completion (==4 ready)

// ---------------------------------------------------------------------------
// scoped sync + packed-FMA helpers
// ---------------------------------------------------------------------------
__device__ __forceinline__ int ld_acquire(const int* p) {
    int v;
    asm volatile("ld.acquire.gpu.global.s32 %0, [%1];" : "=r"(v) : "l"(p) : "memory");
    return v;
}
__device__ __forceinline__ void st_release(int* p, int v) {
    asm volatile("st.release.gpu.global.s32 [%0], %1;" :: "l"(p), "r"(v) : "memory");
}
__device__ __forceinline__ void red_release_add(int* p, int v) {
    asm volatile("red.release.gpu.global.add.s32 [%0], %1;" :: "l"(p), "r"(v) : "memory");
}
__device__ __forceinline__ void spin_ge(const int* p, int want) {
    while (ld_acquire(p) < want) { __nanosleep(60); }
}

#define FMA_F32X2(acc, a, b) \
    asm("fma.rn.f32x2 %0, %1, %2, %0;" : "+l"(acc) : "l"(a), "l"(b))
#define PACK_DUP2(out, f) \
    asm("mov.b64 %0, {%1, %1};" : "=l"(out) : "f"(f))

#define CP_ASYNC16(smem_u32, gptr) \
    asm volatile("cp.async.cg.shared.global [%0], [%1], 16;" :: "r"(smem_u32), "l"(gptr))
#define CP_COMMIT()  asm volatile("cp.async.commit_group;")
#define CP_WAIT(N)   asm volatile("cp.async.wait_group %0;" :: "n"(N))

__device__ __forceinline__ unsigned smem_u32(const void* p) {
    return (unsigned)__cvta_generic_to_shared(p);
}

// bit-strip gather: ascending word/bit order (matches reference list order)
#define STRIP_WORD(acc, mword, rowbase, WP, u) do {            \
    unsigned m_ = (mword);                                      \
    while (m_) {                                                \
        int j_ = __ffs(m_) - 1;                                 \
        (acc) += (WP)[(size_t)((rowbase) + j_) * 512 + (u)];    \
        m_ &= m_ - 1;                                           \
    } } while (0)

// ---------------------------------------------------------------------------
// shared memory (union across roles); GEMM part dominates: 36.9KB
// ---------------------------------------------------------------------------
struct GemmSmem {
    float As[2][128][20];   // [stage][row r][k] padded to 20 (bank-safe, 16B rows)
    float Bs[2][16][128];   // [stage][k][n]
};
struct ScanSmem {
    unsigned mask2[2][16];  // double-buffered own spike mask (lsnn/att)
    unsigned maskB[16];     // wta: zA mask for pop-B gather
    float    red[16];       // wta: per-warp max
};

// ---------------------------------------------------------------------------
// GEMM role: one block = 4 timesteps x 32 batches x 128 output cols, K=512.
// C row r = t*32+b  ->  A row m = b*1000+t.  512 threads, 4x8 per-thread tile.
// ---------------------------------------------------------------------------
__device__ void gemm_role(int g, const float* __restrict__ A,
                          const float* __restrict__ Wk,
                          const float* __restrict__ Wq,
                          const float* __restrict__ Wv,
                          GemmSmem* gs)
{
    const int mchunk = g / 12;
    const int rem    = g % 12;
    const int pop    = rem >> 2;
    const int nt     = rem & 3;
    const float* __restrict__ W = (pop == 0) ? Wk : (pop == 1) ? Wq : Wv;
    float* __restrict__ C = g_I + (size_t)pop * MTOT * NU;

    const int tid = threadIdx.x;
    const int r0 = mchunk * 128;
    const int n0 = nt * 128;
    const int tx = tid & 15;     // 16 col-groups of 8
    const int ty = tid >> 4;     // 32 row-groups of 4

    // A-load duty: row = tid>>2 (0..127), seg = tid&3 (16B each)
    const int arow = tid >> 2;
    const int aseg = tid & 3;
    const int rg   = r0 + arow;
    const int m    = (rg & 31) * 1000 + (rg >> 5);
    const float* Asrc = A + (size_t)m * 512 + aseg * 4;
    // B-load duty: rb = tid>>5 (0..15), cb = tid&31
    const int brb = tid >> 5;
    const int bcb = tid & 31;
    const float* Bsrc = W + (size_t)brb * 512 + n0 + bcb * 4;

    unsigned adstA[2], adstB[2];
#pragma unroll
    for (int s = 0; s < 2; s++) {
        adstA[s] = smem_u32(&gs->As[s][arow][aseg * 4]);
        adstB[s] = smem_u32(&gs->Bs[s][brb][bcb * 4]);
    }

    unsigned long long acc[4][4];
#pragma unroll
    for (int i = 0; i < 4; i++)
#pragma unroll
        for (int j = 0; j < 4; j++) acc[i][j] = 0ull;

    // prologue: stage 0 (k0 = 0)
    CP_ASYNC16(adstA[0], Asrc);
    CP_ASYNC16(adstB[0], Bsrc);
    CP_COMMIT();

    for (int kt = 0; kt < 32; kt++) {
        if (kt < 31) {
            const int k0 = (kt + 1) * 16;
            const int s = (kt + 1) & 1;
            CP_ASYNC16(adstA[s], Asrc + k0);
            CP_ASYNC16(adstB[s], Bsrc + (size_t)k0 * 512);
            CP_COMMIT();
            CP_WAIT(1);
        } else {
            CP_WAIT(0);
        }
        __syncthreads();

        const int s = kt & 1;
#pragma unroll
        for (int kk = 0; kk < 16; kk++) {
            float a0 = gs->As[s][ty * 4 + 0][kk];
            float a1 = gs->As[s][ty * 4 + 1][kk];
            float a2 = gs->As[s][ty * 4 + 2][kk];
            float a3 = gs->As[s][ty * 4 + 3][kk];
            ulonglong2 b01 = *(const ulonglong2*)&gs->Bs[s][kk][tx * 8];
            ulonglong2 b23 = *(const ulonglong2*)&gs->Bs[s][kk][tx * 8 + 4];
            unsigned long long bp0 = b01.x, bp1 = b01.y, bp2 = b23.x, bp3 = b23.y;
            unsigned long long ad;
            PACK_DUP2(ad, a0);
            FMA_F32X2(acc[0][0], ad, bp0); FMA_F32X2(acc[0][1], ad, bp1);
            FMA_F32X2(acc[0][2], ad, bp2); FMA_F32X2(acc[0][3], ad, bp3);
            PACK_DUP2(ad, a1);
            FMA_F32X2(acc[1][0], ad, bp0); FMA_F32X2(acc[1][1], ad, bp1);
            FMA_F32X2(acc[1][2], ad, bp2); FMA_F32X2(acc[1][3], ad, bp3);
            PACK_DUP2(ad, a2);
            FMA_F32X2(acc[2][0], ad, bp0); FMA_F32X2(acc[2][1], ad, bp1);
            FMA_F32X2(acc[2][2], ad, bp2); FMA_F32X2(acc[2][3], ad, bp3);
            PACK_DUP2(ad, a3);
            FMA_F32X2(acc[3][0], ad, bp0); FMA_F32X2(acc[3][1], ad, bp1);
            FMA_F32X2(acc[3][2], ad, bp2); FMA_F32X2(acc[3][3], ad, bp3);
        }
        __syncthreads();
    }

#pragma unroll
    for (int i = 0; i < 4; i++) {
        float* Crow = C + (size_t)(r0 + ty * 4 + i) * 512 + n0 + tx * 8;
        ulonglong2 v0; v0.x = acc[i][0]; v0.y = acc[i][1];
        ulonglong2 v1; v1.x = acc[i][2]; v1.y = acc[i][3];
        *(ulonglong2*)Crow = v0;
        *((ulonglong2*)Crow + 1) = v1;
    }
    __syncthreads();
    if (tid == 0) red_release_add(&g_chunk[pop * 250 + mchunk], 1);
}

// ---------------------------------------------------------------------------
// LSNN role (k,q,v): one block per (pop, batch). thread = neuron. 1 bar/step.
// ---------------------------------------------------------------------------
__device__ void lsnn_role(int p, int b, const float* __restrict__ Wr,
                          float* __restrict__ d_out, ScanSmem* ss)
{
    const float* __restrict__ I = g_I + (size_t)p * MTOT * NU;
    unsigned* __restrict__ spk  = g_spk + ((size_t)p * NB + b) * NT * 16;

    float* __restrict__ out2 = d_out + OUT2_OFF;
    float* __restrict__ out3 = d_out + OUT3_OFF;
    float* __restrict__ out4 = d_out + OUT4_OFF;

    const int tid = threadIdx.x, u = tid, warp = tid >> 5, lane = tid & 31;
    int* flag = &g_flag[p * 32 + b];

    if (tid < 16) { ss->mask2[0][tid] = 0u; }
    __syncthreads();

    float v = 0.f, a = 0.f, z = 0.f;
    int buf = 0;

    for (int t = 0; t < NT; t++) {
        if ((t & 3) == 0) {
            if (tid == 0) spin_ge(&g_chunk[p * 250 + (t >> 2)], 4);
            __syncthreads();
        }

        float acc = I[((size_t)t * 32 + b) * 512 + u];
#pragma unroll 4
        for (int w = 0; w < 16; w++)
            STRIP_WORD(acc, ss->mask2[buf][w], w * 32, Wr, u);

        float a_new = RHO * a + z;
        float thr   = 1.0f + BETA * a_new;
        float v_new = ALPHA * v + acc - z * thr;
        float v_sc  = v_new - thr;
        float z_new = (v_sc > 0.f) ? 1.f : 0.f;

        unsigned bal = __ballot_sync(0xffffffffu, z_new > 0.f);
        if (lane == 0) {
            ss->mask2[buf ^ 1][warp] = bal;
            spk[(size_t)t * 16 + warp] = bal;
        }
        __syncthreads();
        if (tid == 0) st_release(flag, t + 1);

        // outputs AFTER the release: not covered by the fence drain
        const size_t base = (size_t)b * NT + t;
        out2[base * 3072 + (size_t)p * 512 + u] = z_new;
        out3[base * 2048 + (size_t)p * 512 + u] = thr;
        out4[base * 3072 + (size_t)p * 512 + u] = v_sc;

        v = v_new; a = a_new; z = z_new; buf ^= 1;
    }
}

// ---------------------------------------------------------------------------
// WTA role: one block per batch. 3 bars/step.
// ---------------------------------------------------------------------------
__device__ void wta_role(int b, const float* __restrict__ Wa,
                         const float* __restrict__ Wb,
                         float* __restrict__ d_out, ScanSmem* ss)
{
    const uint4* __restrict__ spkK = (const uint4*)(g_spk + (size_t)b * NT * 16);
    const uint4* __restrict__ spkQ = (const uint4*)(g_spk + ((size_t)NB + b) * NT * 16);
    unsigned* __restrict__ zAout   = g_zA + (size_t)b * NT * 16;

    float* __restrict__ out2 = d_out + OUT2_OFF;
    float* __restrict__ out4 = d_out + OUT4_OFF;

    const int tid = threadIdx.x, u = tid, warp = tid >> 5, lane = tid & 31;

    float vA = 0.f, vB = 0.f, zA = 0.f, zB = 0.f;

    for (int t = 0; t < NT; t++) {
        if (tid == 0) spin_ge(&g_flag[0 * 32 + b], t + 1);
        else if (tid == 1) spin_ge(&g_flag[1 * 32 + b], t + 1);
        __syncthreads();                                      // bar 1

        uint4 K0 = spkK[t * 4 + 0], K1 = spkK[t * 4 + 1];
        uint4 K2 = spkK[t * 4 + 2], K3 = spkK[t * 4 + 3];
        uint4 Q0 = spkQ[t * 4 + 0], Q1 = spkQ[t * 4 + 1];
        uint4 Q2 = spkQ[t * 4 + 2], Q3 = spkQ[t * 4 + 3];

        float acc = 0.f;
        STRIP_WORD(acc, K0.x,   0, Wa, u); STRIP_WORD(acc, K0.y,  32, Wa, u);
        STRIP_WORD(acc, K0.z,  64, Wa, u); STRIP_WORD(acc, K0.w,  96, Wa, u);
        STRIP_WORD(acc, K1.x, 128, Wa, u); STRIP_WORD(acc, K1.y, 160, Wa, u);
        STRIP_WORD(acc, K1.z, 192, Wa, u); STRIP_WORD(acc, K1.w, 224, Wa, u);
        STRIP_WORD(acc, K2.x, 256, Wa, u); STRIP_WORD(acc, K2.y, 288, Wa, u);
        STRIP_WORD(acc, K2.z, 320, Wa, u); STRIP_WORD(acc, K2.w, 352, Wa, u);
        STRIP_WORD(acc, K3.x, 384, Wa, u); STRIP_WORD(acc, K3.y, 416, Wa, u);
        STRIP_WORD(acc, K3.z, 448, Wa, u); STRIP_WORD(acc, K3.w, 480, Wa, u);
        STRIP_WORD(acc, Q0.x, 512, Wa, u); STRIP_WORD(acc, Q0.y, 544, Wa, u);
        STRIP_WORD(acc, Q0.z, 576, Wa, u); STRIP_WORD(acc, Q0.w, 608, Wa, u);
        STRIP_WORD(acc, Q1.x, 640, Wa, u); STRIP_WORD(acc, Q1.y, 672, Wa, u);
        STRIP_WORD(acc, Q1.z, 704, Wa, u); STRIP_WORD(acc, Q1.w, 736, Wa, u);
        STRIP_WORD(acc, Q2.x, 768, Wa, u); STRIP_WORD(acc, Q2.y, 800, Wa, u);
        STRIP_WORD(acc, Q2.z, 832, Wa, u); STRIP_WORD(acc, Q2.w, 864, Wa, u);
        STRIP_WORD(acc, Q3.x, 896, Wa, u); STRIP_WORD(acc, Q3.y, 928, Wa, u);
        STRIP_WORD(acc, Q3.z, 960, Wa, u); STRIP_WORD(acc, Q3.w, 992, Wa, u);

        float vA_new = ALPHA * vA + acc - zA;
        float v_sc_A = vA_new - 1.0f;

        float m = vA_new;
#pragma unroll
        for (int o = 16; o > 0; o >>= 1) m = fmaxf(m, __shfl_xor_sync(0xffffffffu, m, o));
        if (lane == 0) ss->red[warp] = m;
        __syncthreads();                                      // bar 2
        // every warp redundantly reduces red[0..15]
        float mm = ss->red[lane & 15];
#pragma unroll
        for (int o = 8; o > 0; o >>= 1) mm = fmaxf(mm, __shfl_xor_sync(0xffffffffu, mm, o));
        // lanes 0..15 and 16..31 both hold the max now

        float winner = (vA_new == mm) ? 1.f : 0.f;
        float zA_new = (v_sc_A > 0.f) ? winner : 0.f;

        unsigned balA = __ballot_sync(0xffffffffu, zA_new > 0.f);
        if (lane == 0) {
            ss->maskB[warp] = balA;
            zAout[(size_t)t * 16 + warp] = balA;
        }
        __syncthreads();                                      // bar 3
        if (tid == 0) st_release(&g_flag[3 * 32 + b], t + 1);

        float accB = 0.f;
#pragma unroll 4
        for (int w = 0; w < 16; w++)
            STRIP_WORD(accB, ss->maskB[w], w * 32, Wb, u);
        float vB_new = ALPHA * vB + accB - zB;
        float v_sc_B = vB_new - 1.0f;
        float zB_new = (v_sc_B > 0.f) ? 1.f : 0.f;

        const size_t base = (size_t)b * NT + t;
        out2[base * 3072 + 3 * 512 + u] = zA_new;
        out2[base * 3072 + 4 * 512 + u] = zB_new;
        out4[base * 3072 + 3 * 512 + u] = v_sc_A;
        out4[base * 3072 + 4 * 512 + u] = v_sc_B;

        vA = vA_new; vB = vB_new; zA = zA_new; zB = zB_new;
    }
}

// ---------------------------------------------------------------------------
// Attention LSNN role: one block per batch. 1 bar/step.
// ---------------------------------------------------------------------------
__device__ void att_role(int b, const float* __restrict__ Win,
                         const float* __restrict__ Wrec,
                         float* __restrict__ d_out, ScanSmem* ss)
{
    const uint4* __restrict__ spkV = (const uint4*)(g_spk + ((size_t)2 * NB + b) * NT * 16);
    const uint4* __restrict__ zAin = (const uint4*)(g_zA + (size_t)b * NT * 16);

    float* __restrict__ out1 = d_out + OUT1_OFF;
    float* __restrict__ out2 = d_out + OUT2_OFF;
    float* __restrict__ out3 = d_out + OUT3_OFF;
    float* __restrict__ out4 = d_out + OUT4_OFF;

    const int tid = threadIdx.x, u = tid, warp = tid >> 5, lane = tid & 31;

    if (tid < 16) ss->mask2[0][tid] = 0u;
    __syncthreads();

    float v = 0.f, a = 0.f, z = 0.f;
    int buf = 0;

    for (int t = 0; t < NT; t++) {
        if (tid == 0) spin_ge(&g_flag[2 * 32 + b], t + 1);
        else if (tid == 1) spin_ge(&g_flag[3 * 32 + b], t + 1);
        __syncthreads();                                      // single bar/step

        uint4 V0 = spkV[t * 4 + 0], V1 = spkV[t * 4 + 1];
        uint4 V2 = spkV[t * 4 + 2], V3 = spkV[t * 4 + 3];
        uint4 A0 = zAin[t * 4 + 0], A1 = zAin[t * 4 + 1];
        uint4 A2 = zAin[t * 4 + 2], A3 = zAin[t * 4 + 3];

        float acc = 0.f;
        STRIP_WORD(acc, V0.x,   0, Win, u); STRIP_WORD(acc, V0.y,  32, Win, u);
        STRIP_WORD(acc, V0.z,  64, Win, u); STRIP_WORD(acc, V0.w,  96, Win, u);
        STRIP_WORD(acc, V1.x, 128, Win, u); STRIP_WORD(acc, V1.y, 160, Win, u);
        STRIP_WORD(acc, V1.z, 192, Win, u); STRIP_WORD(acc, V1.w, 224, Win, u);
        STRIP_WORD(acc, V2.x, 256, Win, u); STRIP_WORD(acc, V2.y, 288, Win, u);
        STRIP_WORD(acc, V2.z, 320, Win, u); STRIP_WORD(acc, V2.w, 352, Win, u);
        STRIP_WORD(acc, V3.x, 384, Win, u); STRIP_WORD(acc, V3.y, 416, Win, u);
        STRIP_WORD(acc, V3.z, 448, Win, u); STRIP_WORD(acc, V3.w, 480, Win, u);
        STRIP_WORD(acc, A0.x, 512, Win, u); STRIP_WORD(acc, A0.y, 544, Win, u);
        STRIP_WORD(acc, A0.z, 576, Win, u); STRIP_WORD(acc, A0.w, 608, Win, u);
        STRIP_WORD(acc, A1.x, 640, Win, u); STRIP_WORD(acc, A1.y, 672, Win, u);
        STRIP_WORD(acc, A1.z, 704, Win, u); STRIP_WORD(acc, A1.w, 736, Win, u);
        STRIP_WORD(acc, A2.x, 768, Win, u); STRIP_WORD(acc, A2.y, 800, Win, u);
        STRIP_WORD(acc, A2.z, 832, Win, u); STRIP_WORD(acc, A2.w, 864, Win, u);
        STRIP_WORD(acc, A3.x, 896, Win, u); STRIP_WORD(acc, A3.y, 928, Win, u);
        STRIP_WORD(acc, A3.z, 960, Win, u); STRIP_WORD(acc, A3.w, 992, Win, u);
#pragma unroll 4
        for (int w = 0; w < 16; w++)
            STRIP_WORD(acc, ss->mask2[buf][w], w * 32, Wrec, u);

        float a_new = RHO * a + z;
        float thr   = 1.0f + BETA * a_new;
        float v_new = ALPHA * v + acc - z * thr;
        float v_sc  = v_new - thr;
        float z_new = (v_sc > 0.f) ? 1.f : 0.f;

        unsigned bal = __ballot_sync(0xffffffffu, z_new > 0.f);
        if (lane == 0) ss->mask2[buf ^ 1][warp] = bal;

        const size_t base = (size_t)b * NT + t;
        out1[base * 512 + u]            = z_new;
        out2[base * 3072 + 5 * 512 + u] = z_new;
        out3[base * 2048 + 3 * 512 + u] = thr;
        out4[base * 3072 + 5 * 512 + u] = v_sc;

        v = v_new; a = a_new; z = z_new; buf ^= 1;
    }
}

// ---------------------------------------------------------------------------
__global__ void reset_kernel()
{
    int i = threadIdx.x;
    if (i < 128) g_flag[i] = 0;
    for (int c = i; c < 750; c += blockDim.x) g_chunk[c] = 0;
}

__global__ __launch_bounds__(512, 2) void fused_kernel(
    const float* __restrict__ x,
    const float* __restrict__ Wk_in, const float* __restrict__ Wk_rec,
    const float* __restrict__ Wq_in, const float* __restrict__ Wq_rec,
    const float* __restrict__ Wv_in, const float* __restrict__ Wv_rec,
    const float* __restrict__ Watt_in, const float* __restrict__ Watt_rec,
    const float* __restrict__ Wwta_a, const float* __restrict__ Wwta_b,
    float* __restrict__ d_out)
{
    __shared__ __align__(16) unsigned char smem_raw[sizeof(GemmSmem)];
    const int bid = blockIdx.x;

    if (bid >= 160) {
        gemm_role(bid - 160, x, Wk_in, Wq_in, Wv_in, (GemmSmem*)smem_raw);
        return;
    }
    ScanSmem* ss = (ScanSmem*)smem_raw;
    if (bid < 96) {
        const int p = bid >> 5, b = bid & 31;
        const float* Wr = (p == 0) ? Wk_rec : (p == 1) ? Wq_rec : Wv_rec;
        lsnn_role(p, b, Wr, d_out, ss);
    } else if (bid < 128) {
        wta_role(bid - 96, Wwta_a, Wwta_b, d_out, ss);
    } else {
        att_role(bid - 128, Watt_in, Watt_rec, d_out, ss);
    }
}

// ---------------------------------------------------------------------------
extern "C" void kernel_launch(void* const* d_in, const int* in_sizes, int n_in,
                              void* d_out, int out_size)
{
    const float* x        = (const float*)d_in[0];
    const float* Wk_in    = (const float*)d_in[1];
    const float* Wk_rec   = (const float*)d_in[2];
    const float* Wq_in    = (const float*)d_in[3];
    const float* Wq_rec   = (const float*)d_in[4];
    const float* Wv_in    = (const float*)d_in[5];
    const float* Wv_rec   = (const float*)d_in[6];
    const float* Watt_in  = (const float*)d_in[7];
    const float* Watt_rec = (const float*)d_in[8];
    const float* Wwta_a   = (const float*)d_in[9];
    const float* Wwta_b   = (const float*)d_in[10];
    float* out = (float*)d_out;

    (void)in_sizes; (void)n_in; (void)out_size;

    reset_kernel<<<1, 1024>>>();
    fused_kernel<<<160 + 3000, 512>>>(x, Wk_in, Wk_rec, Wq_in, Wq_rec,
                                      Wv_in, Wv_rec, Watt_in, Watt_rec,
                                      Wwta_a, Wwta_b, out);
}

// round 4
// speedup vs baseline: 1.4588x; 1.2555x over previous
#include <cuda_runtime.h>
#include <cstdint>

// ---------------------------------------------------------------------------
// SpikingAttention: adaptive-LIF (LSNN) scans + WTA pseudo-softmax
// B=32, T=1000, D=512, U=512
// Single fused kernel: blocks 0..159 = scan roles, blocks 160..3159 = GEMM.
// Gathers use smem index lists + 8-wide load batches (MLP=8), single
// accumulator in ascending index order (bitwise-identical numerics to the
// serial version). Cross-block sync: st.release/ld.acquire (gpu scope).
// ---------------------------------------------------------------------------

#define ALPHA 0.9f
#define RHO   0.995f
#define BETA  1.6f

#define NB 32
#define NT 1000
#define NU 512
#define MTOT (NB*NT)          // 32000

#define OUT1_OFF 0ull
#define OUT2_OFF 16384000ull
#define OUT3_OFF 114688000ull
#define OUT4_OFF 180224000ull

// Scratch
__device__ float    g_I[3ll * MTOT * NU];        // currents, layout [pop][t][b][u]
__device__ unsigned g_spk[3ll * MTOT * 16];      // spike masks [pop][b][t][16]
__device__ unsigned g_zA[(long long)MTOT * 16];  // WTA pop-A spikes [b][t][16]
__device__ int      g_flag[128];                 // per-(pop,b) progress; 0=k,1=q,2=v,3=zA
__device__ int      g_chunk[3 * 250];            // per-(pop, 4t-chunk) GEMM tile completion

// ---------------------------------------------------------------------------
// scoped sync + packed-FMA helpers
// ---------------------------------------------------------------------------
__device__ __forceinline__ int ld_acquire(const int* p) {
    int v;
    asm volatile("ld.acquire.gpu.global.s32 %0, [%1];" : "=r"(v) : "l"(p) : "memory");
    return v;
}
__device__ __forceinline__ void st_release(int* p, int v) {
    asm volatile("st.release.gpu.global.s32 [%0], %1;" :: "l"(p), "r"(v) : "memory");
}
__device__ __forceinline__ void red_release_add(int* p, int v) {
    asm volatile("red.release.gpu.global.add.s32 [%0], %1;" :: "l"(p), "r"(v) : "memory");
}
__device__ __forceinline__ void spin_ge(const int* p, int want) {
    while (ld_acquire(p) < want) { __nanosleep(60); }
}

#define FMA_F32X2(acc, a, b) \
    asm("fma.rn.f32x2 %0, %1, %2, %0;" : "+l"(acc) : "l"(a), "l"(b))
#define PACK_DUP2(out, f) \
    asm("mov.b64 %0, {%1, %1};" : "=l"(out) : "f"(f))

#define CP_ASYNC16(smem_u32, gptr) \
    asm volatile("cp.async.cg.shared.global [%0], [%1], 16;" :: "r"(smem_u32), "l"(gptr))
#define CP_COMMIT()  asm volatile("cp.async.commit_group;")
#define CP_WAIT(N)   asm volatile("cp.async.wait_group %0;" :: "n"(N))

__device__ __forceinline__ unsigned smem_u32(const void* p) {
    return (unsigned)__cvta_generic_to_shared(p);
}

// ---------------------------------------------------------------------------
// shared memory (union across roles); GEMM part dominates: 36.9KB
// ---------------------------------------------------------------------------
struct GemmSmem {
    float As[2][128][20];   // [stage][row][k] padded
    float Bs[2][16][128];   // [stage][k][n]
};
struct ScanSmem {
    unsigned mask2[2][16];        // double-buffered own spike mask (lsnn/att)
    unsigned maskB[16];           // wta: zA mask for pop-B gather
    float    red[16];             // wta: per-warp max
    int      tot;                 // list length
    unsigned short list[1560];    // index list (+8 pad slack)
};

// ---------------------------------------------------------------------------
// List builder: warp 0 only. Each lane contributes one 32-bit word `m`
// (lane order = ascending words). Writes ascending indices; returns total.
// ---------------------------------------------------------------------------
__device__ __forceinline__ int build_list(unsigned m, int bias,
                                          unsigned short* list, int list_off)
{
    const int lane = threadIdx.x & 31;
    int c = __popc(m);
    int inc = c;
#pragma unroll
    for (int o = 1; o < 32; o <<= 1) {
        int v = __shfl_up_sync(0xffffffffu, inc, o);
        if (lane >= o) inc += v;
    }
    int off  = list_off + inc - c;
    int base = bias + lane * 32;
    while (m) {
        int j = __ffs((int)m) - 1;
        list[off++] = (unsigned short)(base + j);
        m &= (m - 1);
    }
    return __shfl_sync(0xffffffffu, inc, 31);
}

// 8-wide batched gather: loads issued in batches of 8 (MLP=8), adds are
// predicated FADDs in ascending order (same numerics as serial version).
// list must be padded with >=8 valid entries beyond n (index 0 is fine).
__device__ __forceinline__ float gather8(const float* __restrict__ W,
                                         const unsigned short* list, int n,
                                         int u, float acc)
{
    for (int i = 0; i < n; i += 8) {
        float w[8];
#pragma unroll
        for (int k = 0; k < 8; k++) {
            int j = list[i + k];
            w[k] = W[(size_t)j * 512 + u];
        }
#pragma unroll
        for (int k = 0; k < 8; k++)
            if (i + k < n) acc += w[k];
    }
    return acc;
}

// variant with two base matrices: idx<1024 -> Win, else Wrec (idx-1024)
__device__ __forceinline__ float gather8_2(const float* __restrict__ Win,
                                           const float* __restrict__ Wrec,
                                           const unsigned short* list, int n,
                                           int u, float acc)
{
    for (int i = 0; i < n; i += 8) {
        float w[8];
#pragma unroll
        for (int k = 0; k < 8; k++) {
            int j = list[i + k];
            const float* base = (j < 1024) ? (Win + (size_t)j * 512)
                                           : (Wrec + (size_t)(j - 1024) * 512);
            w[k] = base[u];
        }
#pragma unroll
        for (int k = 0; k < 8; k++)
            if (i + k < n) acc += w[k];
    }
    return acc;
}

// ---------------------------------------------------------------------------
// GEMM role: one block = 4 timesteps x 32 batches x 128 output cols, K=512.
// C row r = t*32+b  ->  A row m = b*1000+t.  512 threads, 4x8 per-thread tile.
// ---------------------------------------------------------------------------
__device__ void gemm_role(int g, const float* __restrict__ A,
                          const float* __restrict__ Wk,
                          const float* __restrict__ Wq,
                          const float* __restrict__ Wv,
                          GemmSmem* gs)
{
    const int mchunk = g / 12;
    const int rem    = g % 12;
    const int pop    = rem >> 2;
    const int nt     = rem & 3;
    const float* __restrict__ W = (pop == 0) ? Wk : (pop == 1) ? Wq : Wv;
    float* __restrict__ C = g_I + (size_t)pop * MTOT * NU;

    const int tid = threadIdx.x;
    const int r0 = mchunk * 128;
    const int n0 = nt * 128;
    const int tx = tid & 15;
    const int ty = tid >> 4;

    const int arow = tid >> 2;
    const int aseg = tid & 3;
    const int rg   = r0 + arow;
    const int m    = (rg & 31) * 1000 + (rg >> 5);
    const float* Asrc = A + (size_t)m * 512 + aseg * 4;
    const int brb = tid >> 5;
    const int bcb = tid & 31;
    const float* Bsrc = W + (size_t)brb * 512 + n0 + bcb * 4;

    unsigned adstA[2], adstB[2];
#pragma unroll
    for (int s = 0; s < 2; s++) {
        adstA[s] = smem_u32(&gs->As[s][arow][aseg * 4]);
        adstB[s] = smem_u32(&gs->Bs[s][brb][bcb * 4]);
    }

    unsigned long long acc[4][4];
#pragma unroll
    for (int i = 0; i < 4; i++)
#pragma unroll
        for (int j = 0; j < 4; j++) acc[i][j] = 0ull;

    CP_ASYNC16(adstA[0], Asrc);
    CP_ASYNC16(adstB[0], Bsrc);
    CP_COMMIT();

    for (int kt = 0; kt < 32; kt++) {
        if (kt < 31) {
            const int k0 = (kt + 1) * 16;
            const int s = (kt + 1) & 1;
            CP_ASYNC16(adstA[s], Asrc + k0);
            CP_ASYNC16(adstB[s], Bsrc + (size_t)k0 * 512);
            CP_COMMIT();
            CP_WAIT(1);
        } else {
            CP_WAIT(0);
        }
        __syncthreads();

        const int s = kt & 1;
#pragma unroll
        for (int kk = 0; kk < 16; kk++) {
            float a0 = gs->As[s][ty * 4 + 0][kk];
            float a1 = gs->As[s][ty * 4 + 1][kk];
            float a2 = gs->As[s][ty * 4 + 2][kk];
            float a3 = gs->As[s][ty * 4 + 3][kk];
            ulonglong2 b01 = *(const ulonglong2*)&gs->Bs[s][kk][tx * 8];
            ulonglong2 b23 = *(const ulonglong2*)&gs->Bs[s][kk][tx * 8 + 4];
            unsigned long long bp0 = b01.x, bp1 = b01.y, bp2 = b23.x, bp3 = b23.y;
            unsigned long long ad;
            PACK_DUP2(ad, a0);
            FMA_F32X2(acc[0][0], ad, bp0); FMA_F32X2(acc[0][1], ad, bp1);
            FMA_F32X2(acc[0][2], ad, bp2); FMA_F32X2(acc[0][3], ad, bp3);
            PACK_DUP2(ad, a1);
            FMA_F32X2(acc[1][0], ad, bp0); FMA_F32X2(acc[1][1], ad, bp1);
            FMA_F32X2(acc[1][2], ad, bp2); FMA_F32X2(acc[1][3], ad, bp3);
            PACK_DUP2(ad, a2);
            FMA_F32X2(acc[2][0], ad, bp0); FMA_F32X2(acc[2][1], ad, bp1);
            FMA_F32X2(acc[2][2], ad, bp2); FMA_F32X2(acc[2][3], ad, bp3);
            PACK_DUP2(ad, a3);
            FMA_F32X2(acc[3][0], ad, bp0); FMA_F32X2(acc[3][1], ad, bp1);
            FMA_F32X2(acc[3][2], ad, bp2); FMA_F32X2(acc[3][3], ad, bp3);
        }
        __syncthreads();
    }

#pragma unroll
    for (int i = 0; i < 4; i++) {
        float* Crow = C + (size_t)(r0 + ty * 4 + i) * 512 + n0 + tx * 8;
        ulonglong2 v0; v0.x = acc[i][0]; v0.y = acc[i][1];
        ulonglong2 v1; v1.x = acc[i][2]; v1.y = acc[i][3];
        *(ulonglong2*)Crow = v0;
        *((ulonglong2*)Crow + 1) = v1;
    }
    __syncthreads();
    if (tid == 0) red_release_add(&g_chunk[pop * 250 + mchunk], 1);
}

// ---------------------------------------------------------------------------
// LSNN role (k,q,v): one block per (pop, batch). 2 bars/step.
// ---------------------------------------------------------------------------
__device__ void lsnn_role(int p, int b, const float* __restrict__ Wr,
                          float* __restrict__ d_out, ScanSmem* ss)
{
    const float* __restrict__ I = g_I + (size_t)p * MTOT * NU;
    unsigned* __restrict__ spk  = g_spk + ((size_t)p * NB + b) * NT * 16;

    float* __restrict__ out2 = d_out + OUT2_OFF;
    float* __restrict__ out3 = d_out + OUT3_OFF;
    float* __restrict__ out4 = d_out + OUT4_OFF;

    const int tid = threadIdx.x, u = tid, warp = tid >> 5, lane = tid & 31;
    int* flag = &g_flag[p * 32 + b];

    if (tid < 16) ss->mask2[0][tid] = 0u;
    __syncthreads();

    float v = 0.f, a = 0.f, z = 0.f;
    int buf = 0;

    for (int t = 0; t < NT; t++) {
        if (warp == 0) {
            if ((t & 3) == 0 && lane == 0) spin_ge(&g_chunk[p * 250 + (t >> 2)], 4);
            __syncwarp();
            unsigned m = (lane < 16) ? ss->mask2[buf][lane] : 0u;
            int tot = build_list(m, 0, ss->list, 0);
            if (lane < 8) ss->list[tot + lane] = 0;
            if (lane == 0) ss->tot = tot;
        }
        __syncthreads();                                   // B1: list + chunk ready
        const int nsp = ss->tot;

        float acc = I[((size_t)t * 32 + b) * 512 + u];
        acc = gather8(Wr, ss->list, nsp, u, acc);

        float a_new = RHO * a + z;
        float thr   = 1.0f + BETA * a_new;
        float v_new = ALPHA * v + acc - z * thr;
        float v_sc  = v_new - thr;
        float z_new = (v_sc > 0.f) ? 1.f : 0.f;

        unsigned bal = __ballot_sync(0xffffffffu, z_new > 0.f);
        if (lane == 0) {
            ss->mask2[buf ^ 1][warp] = bal;
            spk[(size_t)t * 16 + warp] = bal;
        }
        __syncthreads();                                   // B2: end of step
        if (tid == 0) st_release(flag, t + 1);

        const size_t base = (size_t)b * NT + t;
        out2[base * 3072 + (size_t)p * 512 + u] = z_new;
        out3[base * 2048 + (size_t)p * 512 + u] = thr;
        out4[base * 3072 + (size_t)p * 512 + u] = v_sc;

        v = v_new; a = a_new; z = z_new; buf ^= 1;
    }
}

// ---------------------------------------------------------------------------
// WTA role: one block per batch. 4 bars/step.
// ---------------------------------------------------------------------------
__device__ void wta_role(int b, const float* __restrict__ Wa,
                         const float* __restrict__ Wb,
                         float* __restrict__ d_out, ScanSmem* ss)
{
    const unsigned* __restrict__ spkK = g_spk + (size_t)b * NT * 16;
    const unsigned* __restrict__ spkQ = g_spk + ((size_t)NB + b) * NT * 16;
    unsigned* __restrict__ zAout      = g_zA + (size_t)b * NT * 16;

    float* __restrict__ out2 = d_out + OUT2_OFF;
    float* __restrict__ out4 = d_out + OUT4_OFF;

    const int tid = threadIdx.x, u = tid, warp = tid >> 5, lane = tid & 31;

    float vA = 0.f, vB = 0.f, zA = 0.f, zB = 0.f;

    for (int t = 0; t < NT; t++) {
        if (warp == 0) {
            if (lane == 0) spin_ge(&g_flag[0 * 32 + b], t + 1);
            if (lane == 1) spin_ge(&g_flag[1 * 32 + b], t + 1);
            __syncwarp();
            unsigned m = (lane < 16) ? __ldcg(&spkK[(size_t)t * 16 + lane])
                                     : __ldcg(&spkQ[(size_t)t * 16 + (lane - 16)]);
            int tot = build_list(m, 0, ss->list, 0);       // K:0..511, Q:512..1023
            if (lane < 8) ss->list[tot + lane] = 0;
            if (lane == 0) ss->tot = tot;
        }
        __syncthreads();                                   // B1
        const int nsp = ss->tot;

        float acc = gather8(Wa, ss->list, nsp, u, 0.f);

        float vA_new = ALPHA * vA + acc - zA;
        float v_sc_A = vA_new - 1.0f;

        float m = vA_new;
#pragma unroll
        for (int o = 16; o > 0; o >>= 1) m = fmaxf(m, __shfl_xor_sync(0xffffffffu, m, o));
        if (lane == 0) ss->red[warp] = m;
        __syncthreads();                                   // B2
        float mm = ss->red[lane & 15];
#pragma unroll
        for (int o = 8; o > 0; o >>= 1) mm = fmaxf(mm, __shfl_xor_sync(0xffffffffu, mm, o));

        float winner = (vA_new == mm) ? 1.f : 0.f;
        float zA_new = (v_sc_A > 0.f) ? winner : 0.f;

        unsigned balA = __ballot_sync(0xffffffffu, zA_new > 0.f);
        if (lane == 0) {
            ss->maskB[warp] = balA;
            zAout[(size_t)t * 16 + warp] = balA;
        }
        __syncthreads();                                   // B3
        if (tid == 0) st_release(&g_flag[3 * 32 + b], t + 1);

        // pop-B gather: zA is (near-)one-hot -> direct bit strip, ascending
        float accB = 0.f;
#pragma unroll
        for (int w = 0; w < 16; w++) {
            unsigned mb = ss->maskB[w];
            while (mb) {
                int j = __ffs((int)mb) - 1;
                accB += Wb[(size_t)(w * 32 + j) * 512 + u];
                mb &= mb - 1;
            }
        }
        float vB_new = ALPHA * vB + accB - zB;
        float v_sc_B = vB_new - 1.0f;
        float zB_new = (v_sc_B > 0.f) ? 1.f : 0.f;

        const size_t base = (size_t)b * NT + t;
        out2[base * 3072 + 3 * 512 + u] = zA_new;
        out2[base * 3072 + 4 * 512 + u] = zB_new;
        out4[base * 3072 + 3 * 512 + u] = v_sc_A;
        out4[base * 3072 + 4 * 512 + u] = v_sc_B;

        vA = vA_new; vB = vB_new; zA = zA_new; zB = zB_new;
        __syncthreads();                                   // B4: end (protect maskB/red/list)
    }
}

// ---------------------------------------------------------------------------
// Attention LSNN role: one block per batch. 2 bars/step.
// ---------------------------------------------------------------------------
__device__ void att_role(int b, const float* __restrict__ Win,
                         const float* __restrict__ Wrec,
                         float* __restrict__ d_out, ScanSmem* ss)
{
    const unsigned* __restrict__ spkV = g_spk + ((size_t)2 * NB + b) * NT * 16;
    const unsigned* __restrict__ zAin = g_zA + (size_t)b * NT * 16;

    float* __restrict__ out1 = d_out + OUT1_OFF;
    float* __restrict__ out2 = d_out + OUT2_OFF;
    float* __restrict__ out3 = d_out + OUT3_OFF;
    float* __restrict__ out4 = d_out + OUT4_OFF;

    const int tid = threadIdx.x, u = tid, warp = tid >> 5, lane = tid & 31;

    if (tid < 16) ss->mask2[0][tid] = 0u;
    __syncthreads();

    float v = 0.f, a = 0.f, z = 0.f;
    int buf = 0;

    for (int t = 0; t < NT; t++) {
        if (warp == 0) {
            if (lane == 0) spin_ge(&g_flag[2 * 32 + b], t + 1);
            if (lane == 1) spin_ge(&g_flag[3 * 32 + b], t + 1);
            __syncwarp();
            unsigned m1 = (lane < 16) ? __ldcg(&spkV[(size_t)t * 16 + lane])
                                      : __ldcg(&zAin[(size_t)t * 16 + (lane - 16)]);
            int tot1 = build_list(m1, 0, ss->list, 0);     // V:0..511, zA:512..1023
            unsigned m2 = (lane < 16) ? ss->mask2[buf][lane] : 0u;
            int tot2 = build_list(m2, 1024, ss->list, tot1);   // rec: 1024..1535
            int tot = tot1 + tot2;
            if (lane < 8) ss->list[tot + lane] = 0;
            if (lane == 0) ss->tot = tot;
        }
        __syncthreads();                                   // B1
        const int nsp = ss->tot;

        float acc = gather8_2(Win, Wrec, ss->list, nsp, u, 0.f);

        float a_new = RHO * a + z;
        float thr   = 1.0f + BETA * a_new;
        float v_new = ALPHA * v + acc - z * thr;
        float v_sc  = v_new - thr;
        float z_new = (v_sc > 0.f) ? 1.f : 0.f;

        unsigned bal = __ballot_sync(0xffffffffu, z_new > 0.f);
        if (lane == 0) ss->mask2[buf ^ 1][warp] = bal;

        const size_t base = (size_t)b * NT + t;
        out1[base * 512 + u]            = z_new;
        out2[base * 3072 + 5 * 512 + u] = z_new;
        out3[base * 2048 + 3 * 512 + u] = thr;
        out4[base * 3072 + 5 * 512 + u] = v_sc;

        v = v_new; a = a_new; z = z_new; buf ^= 1;
        __syncthreads();                                   // B2: end
    }
}

// ---------------------------------------------------------------------------
__global__ void reset_kernel()
{
    int i = threadIdx.x;
    if (i < 128) g_flag[i] = 0;
    for (int c = i; c < 750; c += blockDim.x) g_chunk[c] = 0;
}

__global__ __launch_bounds__(512, 2) void fused_kernel(
    const float* __restrict__ x,
    const float* __restrict__ Wk_in, const float* __restrict__ Wk_rec,
    const float* __restrict__ Wq_in, const float* __restrict__ Wq_rec,
    const float* __restrict__ Wv_in, const float* __restrict__ Wv_rec,
    const float* __restrict__ Watt_in, const float* __restrict__ Watt_rec,
    const float* __restrict__ Wwta_a, const float* __restrict__ Wwta_b,
    float* __restrict__ d_out)
{
    __shared__ __align__(16) unsigned char smem_raw[sizeof(GemmSmem)];
    const int bid = blockIdx.x;

    if (bid >= 160) {
        gemm_role(bid - 160, x, Wk_in, Wq_in, Wv_in, (GemmSmem*)smem_raw);
        return;
    }
    ScanSmem* ss = (ScanSmem*)smem_raw;
    if (bid < 96) {
        const int p = bid >> 5, b = bid & 31;
        const float* Wr = (p == 0) ? Wk_rec : (p == 1) ? Wq_rec : Wv_rec;
        lsnn_role(p, b, Wr, d_out, ss);
    } else if (bid < 128) {
        wta_role(bid - 96, Wwta_a, Wwta_b, d_out, ss);
    } else {
        att_role(bid - 128, Watt_in, Watt_rec, d_out, ss);
    }
}

// ---------------------------------------------------------------------------
extern "C" void kernel_launch(void* const* d_in, const int* in_sizes, int n_in,
                              void* d_out, int out_size)
{
    const float* x        = (const float*)d_in[0];
    const float* Wk_in    = (const float*)d_in[1];
    const float* Wk_rec   = (const float*)d_in[2];
    const float* Wq_in    = (const float*)d_in[3];
    const float* Wq_rec   = (const float*)d_in[4];
    const float* Wv_in    = (const float*)d_in[5];
    const float* Wv_rec   = (const float*)d_in[6];
    const float* Watt_in  = (const float*)d_in[7];
    const float* Watt_rec = (const float*)d_in[8];
    const float* Wwta_a   = (const float*)d_in[9];
    const float* Wwta_b   = (const float*)d_in[10];
    float* out = (float*)d_out;

    (void)in_sizes; (void)n_in; (void)out_size;

    reset_kernel<<<1, 1024>>>();
    fused_kernel<<<160 + 3000, 512>>>(x, Wk_in, Wk_rec, Wq_in, Wq_rec,
                                      Wv_in, Wv_rec, Watt_in, Watt_rec,
                                      Wwta_a, Wwta_b, out);
}